// round 1
// baseline (speedup 1.0000x reference)
#include <cuda_runtime.h>
#include <math.h>

#define Bb 2
#define Ss 1024
#define Dd 512
#define Hh 8
#define DKk 64
#define Rr 16
#define Gg 2
#define GDd 32
#define NHh 4
#define KMAX 64

// ---------------- scratch (device globals; no allocation allowed) ----------------
__device__ float g_qtmp[Bb*Hh*Ss*Rr];
__device__ float g_ktmp[Bb*Hh*Ss*Rr];
__device__ float g_qup[Bb*Hh*Ss*DKk];
__device__ float g_kup[Bb*Hh*Ss*DKk];
__device__ float g_vup[Bb*Hh*Ss*DKk];
__device__ unsigned g_hq[Bb*Hh*Gg*Ss];
__device__ unsigned g_hk[Bb*Hh*Gg*Ss];
__device__ unsigned g_sq[Hh*Gg*Ss];
__device__ unsigned g_sk[Hh*Gg*Ss];
__device__ int g_cand[Bb*Hh*Ss*KMAX];
__device__ float g_oh[Bb*Ss*Hh*DKk];

// ---------------- K1: low-rank first stage: q_tmp = query @ Aq, k_tmp = key @ Ak ----
__global__ void k_lowrank(const float* __restrict__ q, const float* __restrict__ k,
                          const float* __restrict__ Aq, const float* __restrict__ Ak) {
    int idx = blockIdx.x * blockDim.x + threadIdx.x;
    if (idx >= Bb*Hh*Ss*Rr) return;
    int r = idx % Rr, s = (idx / Rr) % Ss, h = (idx / (Rr*Ss)) % Hh, b = idx / (Rr*Ss*Hh);
    const float* qr = q + (b*Ss + s)*Dd;
    const float* kr = k + (b*Ss + s)*Dd;
    const float* aq = Aq + h*Dd*Rr + r;
    const float* ak = Ak + h*Dd*Rr + r;
    float accq = 0.f, acck = 0.f;
    for (int d = 0; d < Dd; ++d) {
        accq += qr[d] * aq[d*Rr];
        acck += kr[d] * ak[d*Rr];
    }
    g_qtmp[idx] = accq;
    g_ktmp[idx] = acck;
}

// ---------------- K2: second stage: q_up = q_tmp @ Bq, k_up = k_tmp @ Bk -----------
__global__ void k_upproj(const float* __restrict__ Bq, const float* __restrict__ Bk) {
    int idx = blockIdx.x * blockDim.x + threadIdx.x;
    if (idx >= Bb*Hh*Ss*DKk) return;
    int kk = idx % DKk, s = (idx / DKk) % Ss, h = (idx / (DKk*Ss)) % Hh, b = idx / (DKk*Ss*Hh);
    const float* qt = g_qtmp + ((b*Hh + h)*Ss + s)*Rr;
    const float* kt = g_ktmp + ((b*Hh + h)*Ss + s)*Rr;
    float aq = 0.f, ak = 0.f;
    #pragma unroll
    for (int r = 0; r < Rr; ++r) {
        float wq = Bq[(h*Rr + r)*DKk + kk];
        float wk = Bk[(h*Rr + r)*DKk + kk];
        aq += qt[r] * wq;
        ak += kt[r] * wk;
    }
    g_qup[idx] = aq;
    g_kup[idx] = ak;
}

// ---------------- K3: v_up = value @ Wv (tiled SGEMM per (b,h)) --------------------
__global__ void k_vproj(const float* __restrict__ value, const float* __restrict__ Wv) {
    __shared__ float As[64][33];
    __shared__ float Bs[32][64];
    int bh = blockIdx.x;
    int b = bh / Hh, h = bh % Hh;
    int s0 = blockIdx.y * 64;
    int tid = threadIdx.x;
    int tx = tid & 15, ty = tid >> 4;
    float acc[4][4] = {};
    for (int d0 = 0; d0 < Dd; d0 += 32) {
        for (int t = tid; t < 64*32; t += 256) {
            int r = t >> 5, c = t & 31;
            As[r][c] = value[(b*Ss + s0 + r)*Dd + d0 + c];
        }
        for (int t = tid; t < 32*64; t += 256) {
            int r = t >> 6, c = t & 63;
            Bs[r][c] = Wv[(h*Dd + d0 + r)*DKk + c];
        }
        __syncthreads();
        #pragma unroll
        for (int kk = 0; kk < 32; ++kk) {
            float a[4], bbv[4];
            #pragma unroll
            for (int i2 = 0; i2 < 4; ++i2) a[i2] = As[ty*4 + i2][kk];
            #pragma unroll
            for (int j2 = 0; j2 < 4; ++j2) bbv[j2] = Bs[kk][tx*4 + j2];
            #pragma unroll
            for (int i2 = 0; i2 < 4; ++i2)
                #pragma unroll
                for (int j2 = 0; j2 < 4; ++j2) acc[i2][j2] += a[i2]*bbv[j2];
        }
        __syncthreads();
    }
    #pragma unroll
    for (int i2 = 0; i2 < 4; ++i2)
        #pragma unroll
        for (int j2 = 0; j2 < 4; ++j2)
            g_vup[((b*Hh + h)*Ss + s0 + ty*4 + i2)*DKk + tx*4 + j2] = acc[i2][j2];
}

// ---------------- K4: LSH hashes (4 packed bytes) + sign packs (batch B-1) ---------
__global__ void k_hash(const float* __restrict__ lsh) {
    int idx = blockIdx.x * blockDim.x + threadIdx.x;
    if (idx >= Bb*Hh*Gg*Ss) return;
    int s = idx % Ss, g = (idx / Ss) % Gg, h = (idx / (Ss*Gg)) % Hh, b = idx / (Ss*Gg*Hh);
    const float* qv = g_qup + ((b*Hh + h)*Ss + s)*DKk + g*GDd;
    const float* kv = g_kup + ((b*Hh + h)*Ss + s)*DKk + g*GDd;
    const float* P = lsh + (h*Gg + g)*GDd*NHh;
    float aq0=0,aq1=0,aq2=0,aq3=0, ak0=0,ak1=0,ak2=0,ak3=0;
    unsigned sq = 0, sk = 0;
    #pragma unroll
    for (int d = 0; d < GDd; ++d) {
        float qd = qv[d], kd = kv[d];
        float p0 = P[d*NHh+0], p1 = P[d*NHh+1], p2 = P[d*NHh+2], p3 = P[d*NHh+3];
        aq0 += qd*p0; aq1 += qd*p1; aq2 += qd*p2; aq3 += qd*p3;
        ak0 += kd*p0; ak1 += kd*p1; ak2 += kd*p2; ak3 += kd*p3;
        sq |= (qd > 0.f ? 1u : 0u) << d;
        sk |= (kd > 0.f ? 1u : 0u) << d;
    }
    // jnp.mod(floor(x/4), 64): power-of-2 AND == Python mod on two's complement
    unsigned h0 = (unsigned)(((int)floorf(aq0*0.25f)) & 63);
    unsigned h1 = (unsigned)(((int)floorf(aq1*0.25f)) & 63);
    unsigned h2 = (unsigned)(((int)floorf(aq2*0.25f)) & 63);
    unsigned h3 = (unsigned)(((int)floorf(aq3*0.25f)) & 63);
    g_hq[idx] = h0 | (h1 << 8) | (h2 << 16) | (h3 << 24);
    h0 = (unsigned)(((int)floorf(ak0*0.25f)) & 63);
    h1 = (unsigned)(((int)floorf(ak1*0.25f)) & 63);
    h2 = (unsigned)(((int)floorf(ak2*0.25f)) & 63);
    h3 = (unsigned)(((int)floorf(ak3*0.25f)) & 63);
    g_hk[idx] = h0 | (h1 << 8) | (h2 << 16) | (h3 << 24);
    if (b == Bb - 1) {
        g_sq[(h*Gg + g)*Ss + s] = sq;
        g_sk[(h*Gg + g)*Ss + s] = sk;
    }
}

// ---------------- K5: candidate selection per (b,h,i) ------------------------------
__global__ void k_select() {
    __shared__ float qrow[DKk];
    __shared__ unsigned keys[Ss];
    __shared__ unsigned combMask[Ss/32];
    __shared__ unsigned unionMask[Ss/32];
    __shared__ unsigned hist[256];
    __shared__ int sCnt;
    __shared__ unsigned sDigit;
    __shared__ int sWant;
    __shared__ int sTot;

    int blk = blockIdx.x;
    int i = blk % Ss;
    int h = (blk / Ss) % Hh;
    int b = blk / (Ss*Hh);
    int tid = threadIdx.x;
    int bh = b*Hh + h;

    if (tid < DKk) qrow[tid] = g_qup[(bh*Ss + i)*DKk + tid];
    if (tid < Ss/32) unionMask[tid] = 0u;
    __syncthreads();

    for (int g = 0; g < Gg; ++g) {
        unsigned myh = g_hq[(bh*Gg + g)*Ss + i];
        unsigned mys = g_sq[(h*Gg + g)*Ss + i];
        if (tid == 0) sCnt = 0;
        if (tid < Ss/32) combMask[tid] = 0u;
        __syncthreads();
        int lc = 0;
        for (int j = tid; j < Ss; j += 256) {
            unsigned key = 0u;
            unsigned hk = g_hk[(bh*Gg + g)*Ss + j];
            unsigned x = myh ^ hk;
            bool anyeq = ((x - 0x01010101u) & ~x & 0x80808080u) != 0u;  // any byte equal
            if (anyeq && g_sk[(h*Gg + g)*Ss + j] == mys) {
                const float* kr = g_kup + (bh*Ss + j)*DKk + g*GDd;
                float sdot = 0.f;
                #pragma unroll
                for (int d = 0; d < GDd; ++d) sdot += qrow[g*GDd + d] * kr[d];
                unsigned u = __float_as_uint(sdot);
                key = (u & 0x80000000u) ? ~u : (u | 0x80000000u);  // order-preserving
                atomicOr(&combMask[j >> 5], 1u << (j & 31));
                ++lc;
            }
            keys[j] = key;
        }
        if (lc) atomicAdd(&sCnt, lc);
        __syncthreads();
        unsigned thresh = 0u;
        if (sCnt > KMAX) {
            // MSB radix select: value of the KMAX-th largest key (ties included by >=)
            unsigned prefix = 0u, himask = 0u;
            int want = KMAX;
            for (int pass = 0; pass < 4; ++pass) {
                int shift = 24 - 8*pass;
                hist[tid] = 0u;
                __syncthreads();
                for (int j = tid; j < Ss; j += 256) {
                    unsigned k2 = keys[j];
                    if ((k2 & himask) == prefix) atomicAdd(&hist[(k2 >> shift) & 255], 1u);
                }
                __syncthreads();
                // inclusive suffix sums (Hillis-Steele)
                for (int off = 1; off < 256; off <<= 1) {
                    unsigned add = (tid + off < 256) ? hist[tid + off] : 0u;
                    __syncthreads();
                    hist[tid] += add;
                    __syncthreads();
                }
                unsigned sfx = hist[tid];
                unsigned nxt = (tid < 255) ? hist[tid + 1] : 0u;
                if (sfx >= (unsigned)want && nxt < (unsigned)want) {
                    sDigit = (unsigned)tid;
                    sWant = want - (int)nxt;
                }
                __syncthreads();
                prefix |= sDigit << shift;
                himask |= 0xFFu << shift;
                want = sWant;
                __syncthreads();
            }
            thresh = prefix;
        }
        __syncthreads();
        for (int j = tid; j < Ss; j += 256) {
            if (((combMask[j >> 5] >> (j & 31)) & 1u) && keys[j] >= thresh)
                atomicOr(&unionMask[j >> 5], 1u << (j & 31));
        }
        __syncthreads();
    }

    // extract first KMAX set bits ascending; pad -1
    int outBase = (bh*Ss + i)*KMAX;
    if (tid < 32) {
        unsigned w = unionMask[tid];
        int pc = __popc(w);
        int inc = pc;
        #pragma unroll
        for (int off = 1; off < 32; off <<= 1) {
            int v = __shfl_up_sync(0xffffffffu, inc, off);
            if (tid >= off) inc += v;
        }
        int pos = inc - pc;  // exclusive prefix
        while (w && pos < KMAX) {
            int bit = __ffs(w) - 1;
            w &= w - 1u;
            g_cand[outBase + pos] = tid*32 + bit;
            ++pos;
        }
        if (tid == 31) sTot = inc;
    }
    __syncthreads();
    int tot = min(sTot, KMAX);
    for (int c = tot + tid; c < KMAX; c += 256) g_cand[outBase + c] = -1;
}

// ---------------- K6: sparse attention over candidates -----------------------------
__global__ void k_attn() {
    __shared__ float q[DKk];
    __shared__ float red[KMAX];
    __shared__ float p[KMAX];
    __shared__ int cj[KMAX];
    int blk = blockIdx.x;
    int i = blk % Ss, h = (blk / Ss) % Hh, b = blk / (Ss*Hh);
    int tid = threadIdx.x;
    int bh = b*Hh + h;
    int base = (bh*Ss + i)*KMAX;
    float* orow = g_oh + ((b*Ss + i)*Hh + h)*DKk;
    int j = g_cand[base + tid];
    cj[tid] = j;
    q[tid] = g_qup[(bh*Ss + i)*DKk + tid];
    __syncthreads();
    if (cj[0] < 0) { orow[tid] = 0.f; return; }
    float s = -3.4e38f;
    if (j >= 0) {
        const float* kr = g_kup + (bh*Ss + j)*DKk;
        float acc = 0.f;
        #pragma unroll
        for (int d = 0; d < DKk; ++d) acc += q[d]*kr[d];
        s = acc * 0.125f;  // 1/sqrt(64)
    }
    red[tid] = s; __syncthreads();
    for (int off = 32; off >= 1; off >>= 1) {
        if (tid < off) red[tid] = fmaxf(red[tid], red[tid + off]);
        __syncthreads();
    }
    float mx = red[0]; __syncthreads();
    float e = (j >= 0) ? expf(s - mx) : 0.f;
    red[tid] = e; __syncthreads();
    for (int off = 32; off >= 1; off >>= 1) {
        if (tid < off) red[tid] += red[tid + off];
        __syncthreads();
    }
    float denom = red[0];
    p[tid] = e / denom;
    __syncthreads();
    float acc = 0.f;
    for (int c = 0; c < KMAX; ++c) {
        int jj = cj[c];
        if (jj < 0) break;
        acc += p[c] * g_vup[(bh*Ss + jj)*DKk + tid];
    }
    orow[tid] = acc;
}

// ---------------- K7: out = out_h @ Wo, skipping all-zero rows ---------------------
__global__ void k_out(const float* __restrict__ Wo, float* __restrict__ out) {
    __shared__ float rowv[Hh*DKk];
    __shared__ int sAny;
    int row = blockIdx.x;
    int b = row / Ss, i = row % Ss;
    int tid = threadIdx.x;
    if (tid == 0) {
        int a = 0;
        for (int h = 0; h < Hh; ++h) a |= (g_cand[((b*Hh + h)*Ss + i)*KMAX] >= 0) ? 1 : 0;
        sAny = a;
    }
    __syncthreads();
    float* orow = out + row*Dd;
    if (!sAny) {
        orow[tid] = 0.f;
        orow[tid + 256] = 0.f;
        return;
    }
    for (int t = tid; t < Hh*DKk; t += 256) rowv[t] = g_oh[row*Hh*DKk + t];
    __syncthreads();
    float a0 = 0.f, a1 = 0.f;
    for (int k = 0; k < Hh*DKk; ++k) {
        float rv = rowv[k];
        if (rv == 0.f) continue;  // uniform branch; skips zero-head spans
        a0 += rv * Wo[k*Dd + tid];
        a1 += rv * Wo[k*Dd + tid + 256];
    }
    orow[tid] = a0;
    orow[tid + 256] = a1;
}

// ---------------- launch -----------------------------------------------------------
extern "C" void kernel_launch(void* const* d_in, const int* in_sizes, int n_in,
                              void* d_out, int out_size) {
    const float* query = (const float*)d_in[0];
    const float* key   = (const float*)d_in[1];
    const float* value = (const float*)d_in[2];
    const float* Aq    = (const float*)d_in[3];
    const float* Bq    = (const float*)d_in[4];
    const float* Ak    = (const float*)d_in[5];
    const float* Bk    = (const float*)d_in[6];
    const float* Wv    = (const float*)d_in[7];
    const float* Wo    = (const float*)d_in[8];
    const float* lsh   = (const float*)d_in[9];
    float* out = (float*)d_out;

    k_lowrank<<<(Bb*Hh*Ss*Rr + 255)/256, 256>>>(query, key, Aq, Ak);
    k_upproj<<<(Bb*Hh*Ss*DKk + 255)/256, 256>>>(Bq, Bk);
    k_vproj<<<dim3(Bb*Hh, Ss/64), 256>>>(value, Wv);
    k_hash<<<(Bb*Hh*Gg*Ss + 255)/256, 256>>>(lsh);
    k_select<<<Bb*Hh*Ss, 256>>>();
    k_attn<<<Bb*Hh*Ss, 64>>>();
    k_out<<<Bb*Ss, 256>>>(Wo, out);
}

// round 2
// speedup vs baseline: 1.9329x; 1.9329x over previous
#include <cuda_runtime.h>
#include <math.h>

#define Bb 2
#define Ss 1024
#define Dd 512
#define Hh 8
#define DKk 64
#define Rr 16
#define Gg 2
#define GDd 32
#define NHh 4
#define KMAX 64
#define KSPLIT 4
#define TI 16

// ---------------- scratch (device globals; no allocation allowed) ----------------
__device__ float g_qtmp[KSPLIT*Bb*Ss*Hh*Rr];   // [ks][b*S+s][h*16+r]
__device__ float g_ktmp[KSPLIT*Bb*Ss*Hh*Rr];
__device__ float g_qup[Bb*Hh*Ss*DKk];
__device__ float g_kup[Bb*Hh*Ss*DKk];
__device__ float g_vup[Bb*Hh*Ss*DKk];
__device__ unsigned g_hq[Bb*Hh*Gg*Ss];
__device__ unsigned g_hk[Bb*Hh*Gg*Ss];
__device__ unsigned g_sq[Hh*Gg*Ss];
__device__ unsigned g_sk[Hh*Gg*Ss];
__device__ int g_cand[Bb*Hh*Ss*KMAX];
__device__ float g_oh[Bb*Ss*Hh*DKk];

// ---------------- K1: dual low-rank SGEMM with 4-way K split -----------------------
// out[ks][row][c] = sum_{d in ks-chunk} X[row][d] * W[c/16][d][c%16]
__global__ void k_lowrank_gemm(const float* __restrict__ q, const float* __restrict__ k,
                               const float* __restrict__ Aq, const float* __restrict__ Ak) {
    int z = blockIdx.z;
    int qk = z >> 2, ks = z & 3;
    const float* X = qk ? k : q;
    const float* W = qk ? Ak : Aq;
    float* O = (qk ? g_ktmp : g_qtmp) + ks * (Bb*Ss) * (Hh*Rr);
    int row0 = blockIdx.y * 64;
    int col0 = blockIdx.x * 64;
    int d_base = ks * (Dd / KSPLIT);

    __shared__ float As[64][33];
    __shared__ float Bs[32][64];
    int tid = threadIdx.x;
    int tx = tid & 15, ty = tid >> 4;
    float acc[4][4] = {};

    for (int d0 = 0; d0 < Dd/KSPLIT; d0 += 32) {
        for (int t = tid; t < 64*32; t += 256) {
            int r = t >> 5, c = t & 31;
            As[r][c] = X[(row0 + r)*Dd + d_base + d0 + c];
        }
        for (int t = tid; t < 32*64; t += 256) {
            int dd = t >> 6, cc = t & 63;
            int c = col0 + cc;
            Bs[dd][cc] = W[(c >> 4)*(Dd*Rr) + (d_base + d0 + dd)*Rr + (c & 15)];
        }
        __syncthreads();
        #pragma unroll
        for (int kk = 0; kk < 32; ++kk) {
            float a[4], bv[4];
            #pragma unroll
            for (int i2 = 0; i2 < 4; ++i2) a[i2] = As[ty*4 + i2][kk];
            #pragma unroll
            for (int j2 = 0; j2 < 4; ++j2) bv[j2] = Bs[kk][tx*4 + j2];
            #pragma unroll
            for (int i2 = 0; i2 < 4; ++i2)
                #pragma unroll
                for (int j2 = 0; j2 < 4; ++j2) acc[i2][j2] += a[i2]*bv[j2];
        }
        __syncthreads();
    }
    #pragma unroll
    for (int i2 = 0; i2 < 4; ++i2)
        #pragma unroll
        for (int j2 = 0; j2 < 4; ++j2)
            O[(row0 + ty*4 + i2)*(Hh*Rr) + col0 + tx*4 + j2] = acc[i2][j2];
}

// ---------------- K2: fused up-projection + LSH hash + sign pack -------------------
// block: 4 s-values of one (b,h); blockDim 256; warp = (s_local, group)
__global__ void k_upproj_hash(const float* __restrict__ Bq, const float* __restrict__ Bk,
                              const float* __restrict__ lsh) {
    __shared__ float Bqs[Rr][DKk];
    __shared__ float Bks[Rr][DKk];
    __shared__ float qts[4][Rr];
    __shared__ float kts[4][Rr];
    __shared__ float Ps[Gg*GDd*NHh];

    int blk = blockIdx.x;
    int s0 = (blk % (Ss/4)) * 4;
    int h = (blk / (Ss/4)) % Hh;
    int b = blk / ((Ss/4) * Hh);
    int tid = threadIdx.x;

    for (int t = tid; t < Rr*DKk; t += 256) {
        Bqs[t >> 6][t & 63] = Bq[h*Rr*DKk + t];
        Bks[t >> 6][t & 63] = Bk[h*Rr*DKk + t];
    }
    if (tid < Gg*GDd*NHh) Ps[tid] = lsh[h*(Gg*GDd*NHh) + tid];
    if (tid < 128) {
        int sl = tid >> 5, r = (tid >> 1) & 15, qk = tid & 1;
        int row = b*Ss + s0 + sl;
        const float* base = (qk ? g_ktmp : g_qtmp) + row*(Hh*Rr) + h*Rr + r;
        const int st = (Bb*Ss)*(Hh*Rr);
        float v = base[0] + base[st] + base[2*st] + base[3*st];
        if (qk) kts[sl][r] = v; else qts[sl][r] = v;
    }
    __syncthreads();

    int kk = tid & 63;
    int sl = tid >> 6;
    int s = s0 + sl;
    int bh = b*Hh + h;
    float qv = 0.f, kv = 0.f;
    #pragma unroll
    for (int r = 0; r < Rr; ++r) {
        qv += qts[sl][r] * Bqs[r][kk];
        kv += kts[sl][r] * Bks[r][kk];
    }
    g_qup[(bh*Ss + s)*DKk + kk] = qv;
    g_kup[(bh*Ss + s)*DKk + kk] = kv;

    int g = kk >> 5;
    int d = kk & 31;          // == lane id within warp
    unsigned bq = __ballot_sync(0xffffffffu, qv > 0.f);
    unsigned bk2 = __ballot_sync(0xffffffffu, kv > 0.f);

    float hq[NHh], hk[NHh];
    #pragma unroll
    for (int n = 0; n < NHh; ++n) {
        float p = Ps[(g*GDd + d)*NHh + n];
        hq[n] = qv * p;
        hk[n] = kv * p;
    }
    #pragma unroll
    for (int off = 16; off >= 1; off >>= 1) {
        #pragma unroll
        for (int n = 0; n < NHh; ++n) {
            hq[n] += __shfl_xor_sync(0xffffffffu, hq[n], off);
            hk[n] += __shfl_xor_sync(0xffffffffu, hk[n], off);
        }
    }
    if (d == 0) {
        unsigned pq = 0u, pk = 0u;
        #pragma unroll
        for (int n = 0; n < NHh; ++n) {
            pq |= ((unsigned)(((int)floorf(hq[n]*0.25f)) & 63)) << (8*n);
            pk |= ((unsigned)(((int)floorf(hk[n]*0.25f)) & 63)) << (8*n);
        }
        g_hq[(bh*Gg + g)*Ss + s] = pq;
        g_hk[(bh*Gg + g)*Ss + s] = pk;
        if (b == Bb - 1) {
            g_sq[(h*Gg + g)*Ss + s] = bq;
            g_sk[(h*Gg + g)*Ss + s] = bk2;
        }
    }
}

// ---------------- K3: v_up = value @ Wv (tiled SGEMM per (b,h)) --------------------
__global__ void k_vproj(const float* __restrict__ value, const float* __restrict__ Wv) {
    __shared__ float As[64][33];
    __shared__ float Bs[32][64];
    int bh = blockIdx.x;
    int b = bh / Hh, h = bh % Hh;
    int s0 = blockIdx.y * 64;
    int tid = threadIdx.x;
    int tx = tid & 15, ty = tid >> 4;
    float acc[4][4] = {};
    for (int d0 = 0; d0 < Dd; d0 += 32) {
        for (int t = tid; t < 64*32; t += 256) {
            int r = t >> 5, c = t & 31;
            As[r][c] = value[(b*Ss + s0 + r)*Dd + d0 + c];
        }
        for (int t = tid; t < 32*64; t += 256) {
            int r = t >> 6, c = t & 63;
            Bs[r][c] = Wv[(h*Dd + d0 + r)*DKk + c];
        }
        __syncthreads();
        #pragma unroll
        for (int kk = 0; kk < 32; ++kk) {
            float a[4], bbv[4];
            #pragma unroll
            for (int i2 = 0; i2 < 4; ++i2) a[i2] = As[ty*4 + i2][kk];
            #pragma unroll
            for (int j2 = 0; j2 < 4; ++j2) bbv[j2] = Bs[kk][tx*4 + j2];
            #pragma unroll
            for (int i2 = 0; i2 < 4; ++i2)
                #pragma unroll
                for (int j2 = 0; j2 < 4; ++j2) acc[i2][j2] += a[i2]*bbv[j2];
        }
        __syncthreads();
    }
    #pragma unroll
    for (int i2 = 0; i2 < 4; ++i2)
        #pragma unroll
        for (int j2 = 0; j2 < 4; ++j2)
            g_vup[((b*Hh + h)*Ss + s0 + ty*4 + i2)*DKk + tx*4 + j2] = acc[i2][j2];
}

// ---------------- K5: candidate selection, 16 queries per block --------------------
__global__ void k_select() {
    __shared__ unsigned hks[Ss];
    __shared__ unsigned sks[Ss];
    __shared__ unsigned comb[TI][Ss/32];
    __shared__ unsigned uni[TI][Ss/32];
    __shared__ unsigned myh[TI], mys[TI];
    __shared__ int cnts[TI];
    __shared__ unsigned keys[Ss];
    __shared__ unsigned hist[256];
    __shared__ float qrow[GDd];
    __shared__ unsigned sDigit;
    __shared__ int sWant;

    int blk = blockIdx.x;
    int it0 = (blk % (Ss/TI)) * TI;
    int h = (blk / (Ss/TI)) % Hh;
    int b = blk / ((Ss/TI) * Hh);
    int bh = b*Hh + h;
    int tid = threadIdx.x;
    int warp = tid >> 5, lane = tid & 31;

    for (int t = tid; t < TI*(Ss/32); t += 256) ((unsigned*)uni)[t] = 0u;

    for (int g = 0; g < Gg; ++g) {
        for (int t = tid; t < Ss; t += 256) {
            hks[t] = g_hk[(bh*Gg + g)*Ss + t];
            sks[t] = g_sk[(h*Gg + g)*Ss + t];
        }
        if (tid < TI) {
            myh[tid] = g_hq[(bh*Gg + g)*Ss + it0 + tid];
            mys[tid] = g_sq[(h*Gg + g)*Ss + it0 + tid];
        }
        __syncthreads();

        // each warp matches 2 queries against all 1024 keys (from smem)
        #pragma unroll
        for (int iw = 0; iw < 2; ++iw) {
            int ii = warp*2 + iw;
            unsigned mh = myh[ii], ms = mys[ii];
            int cnt = 0;
            for (int c = 0; c < Ss/32; ++c) {
                int j = c*32 + lane;
                unsigned x = mh ^ hks[j];
                bool m = (((x - 0x01010101u) & ~x & 0x80808080u) != 0u) && (sks[j] == ms);
                unsigned bal = __ballot_sync(0xffffffffu, m);
                if (lane == 0) comb[ii][c] = bal;
                cnt += __popc(bal);
            }
            if (lane == 0) cnts[ii] = cnt;
        }
        __syncthreads();

        // rare path: count > KMAX needs group-sim dots + radix threshold
        for (int ii = 0; ii < TI; ++ii) {
            if (cnts[ii] > KMAX) {
                if (tid < GDd) qrow[tid] = g_qup[(bh*Ss + it0 + ii)*DKk + g*GDd + tid];
                __syncthreads();
                for (int j = tid; j < Ss; j += 256) {
                    unsigned key = 0u;
                    if ((comb[ii][j >> 5] >> (j & 31)) & 1u) {
                        const float* kr = g_kup + (bh*Ss + j)*DKk + g*GDd;
                        float sd = 0.f;
                        #pragma unroll
                        for (int d = 0; d < GDd; ++d) sd += qrow[d]*kr[d];
                        unsigned u = __float_as_uint(sd);
                        key = (u & 0x80000000u) ? ~u : (u | 0x80000000u);
                    }
                    keys[j] = key;
                }
                __syncthreads();
                unsigned prefix = 0u, himask = 0u;
                int want = KMAX;
                for (int pass = 0; pass < 4; ++pass) {
                    int shift = 24 - 8*pass;
                    hist[tid] = 0u;
                    __syncthreads();
                    for (int j = tid; j < Ss; j += 256) {
                        unsigned k2 = keys[j];
                        if ((k2 & himask) == prefix) atomicAdd(&hist[(k2 >> shift) & 255], 1u);
                    }
                    __syncthreads();
                    for (int off = 1; off < 256; off <<= 1) {
                        unsigned add = (tid + off < 256) ? hist[tid + off] : 0u;
                        __syncthreads();
                        hist[tid] += add;
                        __syncthreads();
                    }
                    unsigned sfx = hist[tid];
                    unsigned nxt = (tid < 255) ? hist[tid + 1] : 0u;
                    if (sfx >= (unsigned)want && nxt < (unsigned)want) {
                        sDigit = (unsigned)tid;
                        sWant = want - (int)nxt;
                    }
                    __syncthreads();
                    prefix |= sDigit << shift;
                    himask |= 0xFFu << shift;
                    want = sWant;
                    __syncthreads();
                }
                unsigned thresh = prefix;
                for (int j = tid; j < Ss; j += 256)
                    if (((comb[ii][j >> 5] >> (j & 31)) & 1u) && keys[j] >= thresh)
                        atomicOr(&uni[ii][j >> 5], 1u << (j & 31));
                __syncthreads();
            }
        }

        // common path: cnt <= KMAX  =>  selected == combined
        for (int t = tid; t < TI*(Ss/32); t += 256) {
            int ii = t >> 5, w = t & 31;
            if (cnts[ii] <= KMAX) uni[ii][w] |= comb[ii][w];
        }
        __syncthreads();
    }

    // extraction: first KMAX set bits ascending; pad -1 (warp per 2 queries)
    #pragma unroll
    for (int iw = 0; iw < 2; ++iw) {
        int ii = warp*2 + iw;
        unsigned w32 = uni[ii][lane];
        int pc = __popc(w32);
        int inc = pc;
        #pragma unroll
        for (int off = 1; off < 32; off <<= 1) {
            int v = __shfl_up_sync(0xffffffffu, inc, off);
            if (lane >= off) inc += v;
        }
        int pos = inc - pc;
        int outBase = (bh*Ss + it0 + ii)*KMAX;
        unsigned w2 = w32;
        while (w2 && pos < KMAX) {
            int bit = __ffs(w2) - 1;
            w2 &= w2 - 1u;
            g_cand[outBase + pos] = lane*32 + bit;
            ++pos;
        }
        int tot = __shfl_sync(0xffffffffu, inc, 31);
        tot = min(tot, KMAX);
        for (int c = tot + lane; c < KMAX; c += 32) g_cand[outBase + c] = -1;
    }
}

// ---------------- K6: sparse attention over candidates -----------------------------
__global__ void k_attn() {
    __shared__ float q[DKk];
    __shared__ float red[KMAX];
    __shared__ float p[KMAX];
    __shared__ int cj[KMAX];
    int blk = blockIdx.x;
    int i = blk % Ss, h = (blk / Ss) % Hh, b = blk / (Ss*Hh);
    int tid = threadIdx.x;
    int bh = b*Hh + h;
    int base = (bh*Ss + i)*KMAX;
    float* orow = g_oh + ((b*Ss + i)*Hh + h)*DKk;
    int j = g_cand[base + tid];
    cj[tid] = j;
    q[tid] = g_qup[(bh*Ss + i)*DKk + tid];
    __syncthreads();
    if (cj[0] < 0) { orow[tid] = 0.f; return; }
    float s = -3.4e38f;
    if (j >= 0) {
        const float* kr = g_kup + (bh*Ss + j)*DKk;
        float acc = 0.f;
        #pragma unroll
        for (int d = 0; d < DKk; ++d) acc += q[d]*kr[d];
        s = acc * 0.125f;
    }
    red[tid] = s; __syncthreads();
    for (int off = 32; off >= 1; off >>= 1) {
        if (tid < off) red[tid] = fmaxf(red[tid], red[tid + off]);
        __syncthreads();
    }
    float mx = red[0]; __syncthreads();
    float e = (j >= 0) ? expf(s - mx) : 0.f;
    red[tid] = e; __syncthreads();
    for (int off = 32; off >= 1; off >>= 1) {
        if (tid < off) red[tid] += red[tid + off];
        __syncthreads();
    }
    float denom = red[0];
    p[tid] = e / denom;
    __syncthreads();
    float acc = 0.f;
    for (int c = 0; c < KMAX; ++c) {
        int jj = cj[c];
        if (jj < 0) break;
        acc += p[c] * g_vup[(bh*Ss + jj)*DKk + tid];
    }
    orow[tid] = acc;
}

// ---------------- K7: out = out_h @ Wo, skipping all-zero rows ---------------------
__global__ void k_out(const float* __restrict__ Wo, float* __restrict__ out) {
    __shared__ float rowv[Hh*DKk];
    __shared__ int sAny;
    int row = blockIdx.x;
    int b = row / Ss, i = row % Ss;
    int tid = threadIdx.x;
    if (tid == 0) {
        int a = 0;
        for (int h = 0; h < Hh; ++h) a |= (g_cand[((b*Hh + h)*Ss + i)*KMAX] >= 0) ? 1 : 0;
        sAny = a;
    }
    __syncthreads();
    float* orow = out + row*Dd;
    if (!sAny) {
        orow[tid] = 0.f;
        orow[tid + 256] = 0.f;
        return;
    }
    for (int t = tid; t < Hh*DKk; t += 256) rowv[t] = g_oh[row*Hh*DKk + t];
    __syncthreads();
    float a0 = 0.f, a1 = 0.f;
    for (int k = 0; k < Hh*DKk; ++k) {
        float rv = rowv[k];
        if (rv == 0.f) continue;
        a0 += rv * Wo[k*Dd + tid];
        a1 += rv * Wo[k*Dd + tid + 256];
    }
    orow[tid] = a0;
    orow[tid + 256] = a1;
}

// ---------------- launch -----------------------------------------------------------
extern "C" void kernel_launch(void* const* d_in, const int* in_sizes, int n_in,
                              void* d_out, int out_size) {
    const float* query = (const float*)d_in[0];
    const float* key   = (const float*)d_in[1];
    const float* value = (const float*)d_in[2];
    const float* Aq    = (const float*)d_in[3];
    const float* Bq    = (const float*)d_in[4];
    const float* Ak    = (const float*)d_in[5];
    const float* Bk    = (const float*)d_in[6];
    const float* Wv    = (const float*)d_in[7];
    const float* Wo    = (const float*)d_in[8];
    const float* lsh   = (const float*)d_in[9];
    float* out = (float*)d_out;

    k_lowrank_gemm<<<dim3(2, 32, 8), 256>>>(query, key, Aq, Ak);
    k_vproj<<<dim3(Bb*Hh, Ss/64), 256>>>(value, Wv);
    k_upproj_hash<<<Bb*Hh*(Ss/4), 256>>>(Bq, Bk, lsh);
    k_select<<<Bb*Hh*(Ss/TI), 256>>>();
    k_attn<<<Bb*Hh*Ss, 64>>>();
    k_out<<<Bb*Ss, 256>>>(Wo, out);
}

// round 5
// speedup vs baseline: 3.4985x; 1.8100x over previous
#include <cuda_runtime.h>
#include <math.h>

#define Bb 2
#define Ss 1024
#define Dd 512
#define Hh 8
#define DKk 64
#define Rr 16
#define Gg 2
#define GDd 32
#define NHh 4
#define KMAX 64
#define KSPLIT 4
#define TI 16

// ---------------- scratch (device globals; no allocation allowed) ----------------
__device__ float g_qtmp[KSPLIT*Bb*Ss*Hh*Rr];   // [ks][b*S+s][h*16+r]
__device__ float g_ktmp[KSPLIT*Bb*Ss*Hh*Rr];
__device__ float g_qup[Bb*Hh*Ss*DKk];
__device__ float g_kup[Bb*Hh*Ss*DKk];
__device__ float g_vup[Bb*Hh*Ss*DKk];
__device__ unsigned g_hq[Bb*Hh*Gg*Ss];
__device__ unsigned g_hk[Bb*Hh*Gg*Ss];
__device__ unsigned g_sq[Hh*Gg*Ss];
__device__ unsigned g_sk[Hh*Gg*Ss];
__device__ int g_cand[Bb*Hh*Ss*KMAX];
__device__ int g_cnt[Bb*Hh*Ss];
__device__ unsigned g_tileflag[Hh*(Ss/TI)];
__device__ unsigned g_anyc[Bb*Hh];

// ---------------- K1: dual low-rank SGEMM, 128x128 tiles, 4-way K split ------------
__global__ void k_lowrank_gemm(const float* __restrict__ q, const float* __restrict__ k,
                               const float* __restrict__ Aq, const float* __restrict__ Ak) {
    int qk = blockIdx.z, ks = blockIdx.y;
    const float* X = qk ? k : q;
    const float* W = qk ? Ak : Aq;
    float* O = (qk ? g_ktmp : g_qtmp) + ks * (Bb*Ss) * (Hh*Rr);
    int row0 = blockIdx.x * 128;
    int d_base = ks * (Dd / KSPLIT);

    __shared__ float As[8][128];
    __shared__ float Bs[8][128];
    int tid = threadIdx.x;
    int tx = tid & 15, ty = tid >> 4;
    float acc[8][8] = {};

    int ar = tid >> 1, ac4 = (tid & 1) * 4;
    int bk = tid >> 5, bc4 = (tid & 31) * 4;

    for (int k0 = 0; k0 < Dd/KSPLIT; k0 += 8) {
        float4 av = *(const float4*)&X[(row0 + ar)*Dd + d_base + k0 + ac4];
        As[ac4+0][ar] = av.x; As[ac4+1][ar] = av.y;
        As[ac4+2][ar] = av.z; As[ac4+3][ar] = av.w;
        float4 bv = *(const float4*)&W[(bc4 >> 4)*(Dd*Rr) + (d_base + k0 + bk)*Rr + (bc4 & 15)];
        *(float4*)&Bs[bk][bc4] = bv;
        __syncthreads();
        #pragma unroll
        for (int kk = 0; kk < 8; ++kk) {
            float a[8], bf[8];
            *(float4*)&a[0] = *(const float4*)&As[kk][ty*8];
            *(float4*)&a[4] = *(const float4*)&As[kk][ty*8+4];
            *(float4*)&bf[0] = *(const float4*)&Bs[kk][tx*8];
            *(float4*)&bf[4] = *(const float4*)&Bs[kk][tx*8+4];
            #pragma unroll
            for (int i2 = 0; i2 < 8; ++i2)
                #pragma unroll
                for (int j2 = 0; j2 < 8; ++j2) acc[i2][j2] += a[i2]*bf[j2];
        }
        __syncthreads();
    }
    #pragma unroll
    for (int i2 = 0; i2 < 8; ++i2) {
        float* orow = O + (row0 + ty*8 + i2)*(Hh*Rr) + tx*8;
        *(float4*)&orow[0] = *(float4*)&acc[i2][0];
        *(float4*)&orow[4] = *(float4*)&acc[i2][4];
    }
}

// ---------------- K2: fused up-projection + LSH hash + sign pack -------------------
__global__ void k_upproj_hash(const float* __restrict__ Bq, const float* __restrict__ Bk,
                              const float* __restrict__ lsh) {
    __shared__ float Bqs[Rr][DKk];
    __shared__ float Bks[Rr][DKk];
    __shared__ float qts[4][Rr];
    __shared__ float kts[4][Rr];
    __shared__ float Ps[Gg*GDd*NHh];

    int blk = blockIdx.x;
    int s0 = (blk % (Ss/4)) * 4;
    int h = (blk / (Ss/4)) % Hh;
    int b = blk / ((Ss/4) * Hh);
    int tid = threadIdx.x;

    for (int t = tid; t < Rr*DKk; t += 256) {
        Bqs[t >> 6][t & 63] = Bq[h*Rr*DKk + t];
        Bks[t >> 6][t & 63] = Bk[h*Rr*DKk + t];
    }
    if (tid < Gg*GDd*NHh) Ps[tid] = lsh[h*(Gg*GDd*NHh) + tid];
    if (tid < 128) {
        int sl = tid >> 5, r = (tid >> 1) & 15, qk = tid & 1;
        int row = b*Ss + s0 + sl;
        const float* base = (qk ? g_ktmp : g_qtmp) + row*(Hh*Rr) + h*Rr + r;
        const int st = (Bb*Ss)*(Hh*Rr);
        float v = base[0] + base[st] + base[2*st] + base[3*st];
        if (qk) kts[sl][r] = v; else qts[sl][r] = v;
    }
    __syncthreads();

    int kk = tid & 63;
    int sl = tid >> 6;
    int s = s0 + sl;
    int bh = b*Hh + h;
    float qv = 0.f, kv = 0.f;
    #pragma unroll
    for (int r = 0; r < Rr; ++r) {
        qv += qts[sl][r] * Bqs[r][kk];
        kv += kts[sl][r] * Bks[r][kk];
    }
    g_qup[(bh*Ss + s)*DKk + kk] = qv;
    g_kup[(bh*Ss + s)*DKk + kk] = kv;

    int g = kk >> 5;
    int d = kk & 31;
    unsigned bq = __ballot_sync(0xffffffffu, qv > 0.f);
    unsigned bk2 = __ballot_sync(0xffffffffu, kv > 0.f);

    float hq[NHh], hk[NHh];
    #pragma unroll
    for (int n = 0; n < NHh; ++n) {
        float p = Ps[(g*GDd + d)*NHh + n];
        hq[n] = qv * p;
        hk[n] = kv * p;
    }
    #pragma unroll
    for (int off = 16; off >= 1; off >>= 1) {
        #pragma unroll
        for (int n = 0; n < NHh; ++n) {
            hq[n] += __shfl_xor_sync(0xffffffffu, hq[n], off);
            hk[n] += __shfl_xor_sync(0xffffffffu, hk[n], off);
        }
    }
    if (d == 0) {
        unsigned pq = 0u, pk = 0u;
        #pragma unroll
        for (int n = 0; n < NHh; ++n) {
            pq |= ((unsigned)(((int)floorf(hq[n]*0.25f)) & 63)) << (8*n);
            pk |= ((unsigned)(((int)floorf(hk[n]*0.25f)) & 63)) << (8*n);
        }
        g_hq[(bh*Gg + g)*Ss + s] = pq;
        g_hk[(bh*Gg + g)*Ss + s] = pk;
        if (b == Bb - 1) {
            g_sq[(h*Gg + g)*Ss + s] = bq;
            g_sk[(h*Gg + g)*Ss + s] = bk2;
        }
    }
}

// ---------------- K3: trie prefilter — O(S) sign matching, provably bounded --------
__global__ void k_trie() {
    __shared__ unsigned tsign[2048];
    __shared__ int tj[2048];
    __shared__ unsigned rowflag[Ss/32];
    __shared__ int fallback;
    int h = blockIdx.x;
    int tid = threadIdx.x;
    if (h == 0 && tid < Bb*Hh) g_anyc[tid] = 0u;   // reset gates each run
    if (tid == 0) fallback = 0;
    for (int t = tid; t < Ss/32; t += 256) rowflag[t] = 0u;
    for (int g = 0; g < Gg; ++g) {
        for (int t = tid; t < 2048; t += 256) tj[t] = 0;
        __syncthreads();
        for (int j = tid; j < Ss; j += 256) {
            unsigned s = g_sk[(h*Gg + g)*Ss + j];
            unsigned slot = (s * 2654435761u >> 16) & 2047u;
            bool ok = false;
            for (int p = 0; p < 4096; ++p) {          // bounded: free slot exists (LF=0.5)
                if (atomicCAS(&tj[slot], 0, (int)j + 1) == 0) { tsign[slot] = s; ok = true; break; }
                slot = (slot + 1) & 2047u;
            }
            if (!ok) atomicExch(&fallback, 1);        // unreachable; conservative-correct
        }
        __syncthreads();
        for (int i = tid; i < Ss; i += 256) {
            unsigned s = g_sq[(h*Gg + g)*Ss + i];
            unsigned slot = (s * 2654435761u >> 16) & 2047u;
            bool m = true;                             // cap exceeded -> conservative match
            for (int p = 0; p < 2048; ++p) {
                int occ = tj[slot];
                if (occ == 0) { m = false; break; }
                if (tsign[slot] == s) { m = true; break; }
                slot = (slot + 1) & 2047u;
            }
            if (m) atomicOr(&rowflag[i >> 5], 1u << (i & 31));
        }
        __syncthreads();
    }
    if (tid < Ss/TI) {
        unsigned w = rowflag[tid >> 1];
        unsigned bits = (w >> ((tid & 1) * 16)) & 0xFFFFu;
        g_tileflag[h*(Ss/TI) + tid] = (bits || fallback) ? 1u : 0u;
    }
}

// ---------------- K4: candidate selection, tile-gated ------------------------------
__global__ void k_select() {
    __shared__ unsigned hks[Ss];
    __shared__ unsigned sks[Ss];
    __shared__ unsigned comb[TI][Ss/32];
    __shared__ unsigned uni[TI][Ss/32];
    __shared__ unsigned myh[TI], mys[TI];
    __shared__ int cnts[TI];
    __shared__ unsigned keys[Ss];
    __shared__ unsigned hist[256];
    __shared__ float qrow[GDd];
    __shared__ unsigned sDigit;
    __shared__ int sWant;

    int blk = blockIdx.x;
    int tile = blk % (Ss/TI);
    int it0 = tile * TI;
    int h = (blk / (Ss/TI)) % Hh;
    int b = blk / ((Ss/TI) * Hh);
    int bh = b*Hh + h;
    int tid = threadIdx.x;
    int warp = tid >> 5, lane = tid & 31;

    if (!g_tileflag[h*(Ss/TI) + tile]) {       // no trie match in tile -> 0 candidates
        if (tid < TI) g_cnt[bh*Ss + it0 + tid] = 0;
        return;
    }

    for (int t = tid; t < TI*(Ss/32); t += 256) ((unsigned*)uni)[t] = 0u;

    for (int g = 0; g < Gg; ++g) {
        for (int t = tid; t < Ss; t += 256) {
            hks[t] = g_hk[(bh*Gg + g)*Ss + t];
            sks[t] = g_sk[(h*Gg + g)*Ss + t];
        }
        if (tid < TI) {
            myh[tid] = g_hq[(bh*Gg + g)*Ss + it0 + tid];
            mys[tid] = g_sq[(h*Gg + g)*Ss + it0 + tid];
        }
        __syncthreads();

        #pragma unroll
        for (int iw = 0; iw < 2; ++iw) {
            int ii = warp*2 + iw;
            unsigned mh = myh[ii], ms = mys[ii];
            int cnt = 0;
            for (int c = 0; c < Ss/32; ++c) {
                int j = c*32 + lane;
                unsigned x = mh ^ hks[j];
                bool m = (((x - 0x01010101u) & ~x & 0x80808080u) != 0u) && (sks[j] == ms);
                unsigned bal = __ballot_sync(0xffffffffu, m);
                if (lane == 0) comb[ii][c] = bal;
                cnt += __popc(bal);
            }
            if (lane == 0) cnts[ii] = cnt;
        }
        __syncthreads();

        // rare path: count > KMAX needs group-sim dots + radix threshold
        for (int ii = 0; ii < TI; ++ii) {
            if (cnts[ii] > KMAX) {
                if (tid < GDd) qrow[tid] = g_qup[(bh*Ss + it0 + ii)*DKk + g*GDd + tid];
                __syncthreads();
                for (int j = tid; j < Ss; j += 256) {
                    unsigned key = 0u;
                    if ((comb[ii][j >> 5] >> (j & 31)) & 1u) {
                        const float* kr = g_kup + (bh*Ss + j)*DKk + g*GDd;
                        float sd = 0.f;
                        #pragma unroll
                        for (int d = 0; d < GDd; ++d) sd += qrow[d]*kr[d];
                        unsigned u = __float_as_uint(sd);
                        key = (u & 0x80000000u) ? ~u : (u | 0x80000000u);
                    }
                    keys[j] = key;
                }
                __syncthreads();
                unsigned prefix = 0u, himask = 0u;
                int want = KMAX;
                for (int pass = 0; pass < 4; ++pass) {
                    int shift = 24 - 8*pass;
                    hist[tid] = 0u;
                    __syncthreads();
                    for (int j = tid; j < Ss; j += 256) {
                        unsigned k2 = keys[j];
                        if ((k2 & himask) == prefix) atomicAdd(&hist[(k2 >> shift) & 255], 1u);
                    }
                    __syncthreads();
                    for (int off = 1; off < 256; off <<= 1) {
                        unsigned add = (tid + off < 256) ? hist[tid + off] : 0u;
                        __syncthreads();
                        hist[tid] += add;
                        __syncthreads();
                    }
                    unsigned sfx = hist[tid];
                    unsigned nxt = (tid < 255) ? hist[tid + 1] : 0u;
                    if (sfx >= (unsigned)want && nxt < (unsigned)want) {
                        sDigit = (unsigned)tid;
                        sWant = want - (int)nxt;
                    }
                    __syncthreads();
                    prefix |= sDigit << shift;
                    himask |= 0xFFu << shift;
                    want = sWant;
                    __syncthreads();
                }
                unsigned thresh = prefix;
                for (int j = tid; j < Ss; j += 256)
                    if (((comb[ii][j >> 5] >> (j & 31)) & 1u) && keys[j] >= thresh)
                        atomicOr(&uni[ii][j >> 5], 1u << (j & 31));
                __syncthreads();
            }
        }

        for (int t = tid; t < TI*(Ss/32); t += 256) {
            int ii = t >> 5, w = t & 31;
            if (cnts[ii] <= KMAX) uni[ii][w] |= comb[ii][w];
        }
        __syncthreads();
    }

    #pragma unroll
    for (int iw = 0; iw < 2; ++iw) {
        int ii = warp*2 + iw;
        unsigned w32 = uni[ii][lane];
        int pc = __popc(w32);
        int inc = pc;
        #pragma unroll
        for (int off = 1; off < 32; off <<= 1) {
            int v = __shfl_up_sync(0xffffffffu, inc, off);
            if (lane >= off) inc += v;
        }
        int pos = inc - pc;
        int outBase = (bh*Ss + it0 + ii)*KMAX;
        unsigned w2 = w32;
        while (w2 && pos < KMAX) {
            int bit = __ffs(w2) - 1;
            w2 &= w2 - 1u;
            g_cand[outBase + pos] = lane*32 + bit;
            ++pos;
        }
        int tot = __shfl_sync(0xffffffffu, inc, 31);
        tot = min(tot, KMAX);
        if (lane == 0) {
            g_cnt[bh*Ss + it0 + ii] = tot;
            if (tot > 0) atomicOr(&g_anyc[bh], 1u);
        }
    }
}

// ---------------- K5: v_up = value @ Wv, gated per (b,h) ---------------------------
__global__ void k_vproj(const float* __restrict__ value, const float* __restrict__ Wv) {
    int bh = blockIdx.x;
    if (!g_anyc[bh]) return;                    // output never read -> skip
    __shared__ float As[64][33];
    __shared__ float Bs[32][64];
    int b = bh / Hh, h = bh % Hh;
    int s0 = blockIdx.y * 64;
    int tid = threadIdx.x;
    int tx = tid & 15, ty = tid >> 4;
    float acc[4][4] = {};
    for (int d0 = 0; d0 < Dd; d0 += 32) {
        for (int t = tid; t < 64*32; t += 256) {
            int r = t >> 5, c = t & 31;
            As[r][c] = value[(b*Ss + s0 + r)*Dd + d0 + c];
        }
        for (int t = tid; t < 32*64; t += 256) {
            int r = t >> 6, c = t & 63;
            Bs[r][c] = Wv[(h*Dd + d0 + r)*DKk + c];
        }
        __syncthreads();
        #pragma unroll
        for (int kk = 0; kk < 32; ++kk) {
            float a[4], bbv[4];
            #pragma unroll
            for (int i2 = 0; i2 < 4; ++i2) a[i2] = As[ty*4 + i2][kk];
            #pragma unroll
            for (int j2 = 0; j2 < 4; ++j2) bbv[j2] = Bs[kk][tx*4 + j2];
            #pragma unroll
            for (int i2 = 0; i2 < 4; ++i2)
                #pragma unroll
                for (int j2 = 0; j2 < 4; ++j2) acc[i2][j2] += a[i2]*bbv[j2];
        }
        __syncthreads();
    }
    #pragma unroll
    for (int i2 = 0; i2 < 4; ++i2)
        #pragma unroll
        for (int j2 = 0; j2 < 4; ++j2)
            g_vup[((b*Hh + h)*Ss + s0 + ty*4 + i2)*DKk + tx*4 + j2] = acc[i2][j2];
}

// ---------------- K6: fused sparse attention + output GEMM per (b,i) row -----------
__global__ void k_attn_out(const float* __restrict__ Wo, float* __restrict__ out) {
    __shared__ int cnt8[Hh];
    __shared__ float rowv[Hh*DKk];
    __shared__ float q64[DKk];
    __shared__ float red[DKk];
    __shared__ float pp[KMAX];
    __shared__ int cj[KMAX];
    int row = blockIdx.x;
    int b = row >> 10, i = row & 1023;
    int tid = threadIdx.x;
    if (tid < Hh) cnt8[tid] = g_cnt[(b*Hh + tid)*Ss + i];
    __syncthreads();
    int any = 0;
    #pragma unroll
    for (int h2 = 0; h2 < Hh; ++h2) any |= cnt8[h2];
    float* orow = out + row*Dd;
    if (!any) {
        if (tid < 128) ((float4*)orow)[tid] = make_float4(0.f, 0.f, 0.f, 0.f);
        return;
    }
    for (int h2 = 0; h2 < Hh; ++h2) {
        int cn = cnt8[h2];
        if (cn == 0) {
            if (tid < DKk) rowv[h2*DKk + tid] = 0.f;
            __syncthreads();
            continue;
        }
        int bh = b*Hh + h2;
        if (tid < DKk) q64[tid] = g_qup[(bh*Ss + i)*DKk + tid];
        if (tid < cn) cj[tid] = g_cand[(bh*Ss + i)*KMAX + tid];
        __syncthreads();
        float s = -3.4e38f;
        if (tid < cn) {
            const float* kr = g_kup + (bh*Ss + cj[tid])*DKk;
            float acc = 0.f;
            #pragma unroll
            for (int d = 0; d < DKk; ++d) acc += q64[d]*kr[d];
            s = acc * 0.125f;
        }
        if (tid < DKk) red[tid] = s;
        __syncthreads();
        for (int off = 32; off >= 1; off >>= 1) {
            if (tid < off) red[tid] = fmaxf(red[tid], red[tid + off]);
            __syncthreads();
        }
        float mx = red[0];
        __syncthreads();
        float e = (tid < cn) ? expf(s - mx) : 0.f;
        if (tid < DKk) red[tid] = e;
        __syncthreads();
        for (int off = 32; off >= 1; off >>= 1) {
            if (tid < off) red[tid] += red[tid + off];
            __syncthreads();
        }
        float denom = red[0];
        if (tid < DKk) pp[tid] = e / denom;
        __syncthreads();
        if (tid < DKk) {
            float acc = 0.f;
            for (int c = 0; c < cn; ++c) acc += pp[c]*g_vup[(bh*Ss + cj[c])*DKk + tid];
            rowv[h2*DKk + tid] = acc;
        }
        __syncthreads();
    }
    float a0 = 0.f, a1 = 0.f;
    for (int k2 = 0; k2 < Hh*DKk; ++k2) {
        float rv = rowv[k2];
        if (rv == 0.f) continue;
        a0 += rv * Wo[k2*Dd + tid];
        a1 += rv * Wo[k2*Dd + tid + 256];
    }
    orow[tid] = a0;
    orow[tid + 256] = a1;
}

// ---------------- launch -----------------------------------------------------------
extern "C" void kernel_launch(void* const* d_in, const int* in_sizes, int n_in,
                              void* d_out, int out_size) {
    const float* query = (const float*)d_in[0];
    const float* key   = (const float*)d_in[1];
    const float* value = (const float*)d_in[2];
    const float* Aq    = (const float*)d_in[3];
    const float* Bq    = (const float*)d_in[4];
    const float* Ak    = (const float*)d_in[5];
    const float* Bk    = (const float*)d_in[6];
    const float* Wv    = (const float*)d_in[7];
    const float* Wo    = (const float*)d_in[8];
    const float* lsh   = (const float*)d_in[9];
    float* out = (float*)d_out;

    k_lowrank_gemm<<<dim3(16, KSPLIT, 2), 256>>>(query, key, Aq, Ak);
    k_upproj_hash<<<Bb*Hh*(Ss/4), 256>>>(Bq, Bk, lsh);
    k_trie<<<Hh, 256>>>();
    k_select<<<Bb*Hh*(Ss/TI), 256>>>();
    k_vproj<<<dim3(Bb*Hh, Ss/64), 256>>>(value, Wv);
    k_attn_out<<<Bb*Ss, 256>>>(Wo, out);
}

// round 6
// speedup vs baseline: 3.6991x; 1.0573x over previous
#include <cuda_runtime.h>
#include <math.h>

#define Bb 2
#define Ss 1024
#define Dd 512
#define Hh 8
#define DKk 64
#define Rr 16
#define Gg 2
#define GDd 32
#define NHh 4
#define KMAX 64
#define KSPLIT 4
#define TI 16

// ---------------- scratch (device globals; no allocation allowed) ----------------
__device__ float g_qtmp[KSPLIT*Bb*Ss*Hh*Rr];   // [ks][b*S+s][h*16+r]
__device__ float g_ktmp[KSPLIT*Bb*Ss*Hh*Rr];
__device__ float g_qup[Bb*Hh*Ss*DKk];
__device__ float g_kup[Bb*Hh*Ss*DKk];
__device__ unsigned g_hq[Bb*Hh*Gg*Ss];
__device__ unsigned g_hk[Bb*Hh*Gg*Ss];
__device__ unsigned g_sq[Hh*Gg*Ss];
__device__ unsigned g_sk[Hh*Gg*Ss];
__device__ int g_cand[Bb*Hh*Ss*KMAX];
__device__ int g_cnt[Bb*Hh*Ss];
__device__ int g_work[Hh*(Ss/TI)];
__device__ int g_nwork;

// ---------------- K1: dual low-rank SGEMM, 128x128 tiles, 4-way K split ------------
__global__ void k_lowrank_gemm(const float* __restrict__ q, const float* __restrict__ k,
                               const float* __restrict__ Aq, const float* __restrict__ Ak) {
    int qk = blockIdx.z, ks = blockIdx.y;
    const float* X = qk ? k : q;
    const float* W = qk ? Ak : Aq;
    float* O = (qk ? g_ktmp : g_qtmp) + ks * (Bb*Ss) * (Hh*Rr);
    int row0 = blockIdx.x * 128;
    int d_base = ks * (Dd / KSPLIT);

    __shared__ float As[8][128];
    __shared__ float Bs[8][128];
    int tid = threadIdx.x;
    int tx = tid & 15, ty = tid >> 4;
    float acc[8][8] = {};

    int ar = tid >> 1, ac4 = (tid & 1) * 4;
    int bk = tid >> 5, bc4 = (tid & 31) * 4;

    for (int k0 = 0; k0 < Dd/KSPLIT; k0 += 8) {
        float4 av = *(const float4*)&X[(row0 + ar)*Dd + d_base + k0 + ac4];
        As[ac4+0][ar] = av.x; As[ac4+1][ar] = av.y;
        As[ac4+2][ar] = av.z; As[ac4+3][ar] = av.w;
        float4 bv = *(const float4*)&W[(bc4 >> 4)*(Dd*Rr) + (d_base + k0 + bk)*Rr + (bc4 & 15)];
        *(float4*)&Bs[bk][bc4] = bv;
        __syncthreads();
        #pragma unroll
        for (int kk = 0; kk < 8; ++kk) {
            float a[8], bf[8];
            *(float4*)&a[0] = *(const float4*)&As[kk][ty*8];
            *(float4*)&a[4] = *(const float4*)&As[kk][ty*8+4];
            *(float4*)&bf[0] = *(const float4*)&Bs[kk][tx*8];
            *(float4*)&bf[4] = *(const float4*)&Bs[kk][tx*8+4];
            #pragma unroll
            for (int i2 = 0; i2 < 8; ++i2)
                #pragma unroll
                for (int j2 = 0; j2 < 8; ++j2) acc[i2][j2] += a[i2]*bf[j2];
        }
        __syncthreads();
    }
    #pragma unroll
    for (int i2 = 0; i2 < 8; ++i2) {
        float* orow = O + (row0 + ty*8 + i2)*(Hh*Rr) + tx*8;
        *(float4*)&orow[0] = *(float4*)&acc[i2][0];
        *(float4*)&orow[4] = *(float4*)&acc[i2][4];
    }
}

// ---------------- K2: fused up-projection + LSH hash + sign pack (16 s/block) ------
__global__ void k_upproj_hash(const float* __restrict__ Bq, const float* __restrict__ Bk,
                              const float* __restrict__ lsh) {
    __shared__ float Bqs[Rr][DKk];
    __shared__ float Bks[Rr][DKk];
    __shared__ float qts[4][Rr];
    __shared__ float kts[4][Rr];
    __shared__ float Ps[Gg*GDd*NHh];

    int blk = blockIdx.x;
    int s0 = (blk % (Ss/16)) * 16;
    int h = (blk / (Ss/16)) % Hh;
    int b = blk / ((Ss/16) * Hh);
    int tid = threadIdx.x;

    if (blk == 0 && tid == 0) g_nwork = 0;     // reset worklist for k_trie
    for (int t = tid; t < Rr*DKk; t += 256) {
        Bqs[t >> 6][t & 63] = Bq[h*Rr*DKk + t];
        Bks[t >> 6][t & 63] = Bk[h*Rr*DKk + t];
    }
    if (tid < Gg*GDd*NHh) Ps[tid] = lsh[h*(Gg*GDd*NHh) + tid];

    int kk = tid & 63;
    int sl2 = tid >> 6;
    int g = kk >> 5;
    int d = kk & 31;
    int bh = b*Hh + h;

    for (int ss = 0; ss < 16; ss += 4) {
        if (tid < 128) {
            int sl = tid >> 5, r = (tid >> 1) & 15, qk = tid & 1;
            int row = b*Ss + s0 + ss + sl;
            const float* base = (qk ? g_ktmp : g_qtmp) + row*(Hh*Rr) + h*Rr + r;
            const int st = (Bb*Ss)*(Hh*Rr);
            float v = base[0] + base[st] + base[2*st] + base[3*st];
            if (qk) kts[sl][r] = v; else qts[sl][r] = v;
        }
        __syncthreads();

        int s = s0 + ss + sl2;
        float qv = 0.f, kv = 0.f;
        #pragma unroll
        for (int r = 0; r < Rr; ++r) {
            qv += qts[sl2][r] * Bqs[r][kk];
            kv += kts[sl2][r] * Bks[r][kk];
        }
        g_qup[(bh*Ss + s)*DKk + kk] = qv;
        g_kup[(bh*Ss + s)*DKk + kk] = kv;

        unsigned bq = __ballot_sync(0xffffffffu, qv > 0.f);
        unsigned bk2 = __ballot_sync(0xffffffffu, kv > 0.f);

        float hq[NHh], hk[NHh];
        #pragma unroll
        for (int n = 0; n < NHh; ++n) {
            float p = Ps[(g*GDd + d)*NHh + n];
            hq[n] = qv * p;
            hk[n] = kv * p;
        }
        #pragma unroll
        for (int off = 16; off >= 1; off >>= 1) {
            #pragma unroll
            for (int n = 0; n < NHh; ++n) {
                hq[n] += __shfl_xor_sync(0xffffffffu, hq[n], off);
                hk[n] += __shfl_xor_sync(0xffffffffu, hk[n], off);
            }
        }
        if (d == 0) {
            unsigned pq = 0u, pk = 0u;
            #pragma unroll
            for (int n = 0; n < NHh; ++n) {
                pq |= ((unsigned)(((int)floorf(hq[n]*0.25f)) & 63)) << (8*n);
                pk |= ((unsigned)(((int)floorf(hk[n]*0.25f)) & 63)) << (8*n);
            }
            g_hq[(bh*Gg + g)*Ss + s] = pq;
            g_hk[(bh*Gg + g)*Ss + s] = pk;
            if (b == Bb - 1) {
                g_sq[(h*Gg + g)*Ss + s] = bq;
                g_sk[(h*Gg + g)*Ss + s] = bk2;
            }
        }
        __syncthreads();
    }
}

// ---------------- K3: trie prefilter + worklist build + g_cnt zeroing --------------
__global__ void k_trie() {
    __shared__ unsigned tsign[2048];
    __shared__ int tj[2048];
    __shared__ unsigned rowflag[Ss/32];
    __shared__ int fallback;
    __shared__ unsigned flags[Ss/TI];
    int h = blockIdx.x;
    int tid = threadIdx.x;
    if (tid == 0) fallback = 0;
    for (int t = tid; t < Ss/32; t += 256) rowflag[t] = 0u;
    for (int g = 0; g < Gg; ++g) {
        for (int t = tid; t < 2048; t += 256) tj[t] = 0;
        __syncthreads();
        for (int j = tid; j < Ss; j += 256) {
            unsigned s = g_sk[(h*Gg + g)*Ss + j];
            unsigned slot = (s * 2654435761u >> 16) & 2047u;
            bool ok = false;
            for (int p = 0; p < 4096; ++p) {          // bounded: free slot exists (LF=0.5)
                if (atomicCAS(&tj[slot], 0, (int)j + 1) == 0) { tsign[slot] = s; ok = true; break; }
                slot = (slot + 1) & 2047u;
            }
            if (!ok) atomicExch(&fallback, 1);        // unreachable; conservative-correct
        }
        __syncthreads();
        for (int i = tid; i < Ss; i += 256) {
            unsigned s = g_sq[(h*Gg + g)*Ss + i];
            unsigned slot = (s * 2654435761u >> 16) & 2047u;
            bool m = true;                             // cap exceeded -> conservative match
            for (int p = 0; p < 2048; ++p) {
                int occ = tj[slot];
                if (occ == 0) { m = false; break; }
                if (tsign[slot] == s) { m = true; break; }
                slot = (slot + 1) & 2047u;
            }
            if (m) atomicOr(&rowflag[i >> 5], 1u << (i & 31));
        }
        __syncthreads();
    }
    if (tid < Ss/TI) {
        unsigned w = rowflag[tid >> 1];
        unsigned bits = (w >> ((tid & 1) * 16)) & 0xFFFFu;
        unsigned f = (bits || fallback) ? 1u : 0u;
        flags[tid] = f;
        if (f) {
            int p = atomicAdd(&g_nwork, 1);
            g_work[p] = (h << 6) | tid;               // tile index fits 6 bits (64 tiles)
        }
    }
    __syncthreads();
    for (int t = tid; t < Bb*Ss; t += 256) {
        int b2 = t >> 10, s = t & 1023;
        if (!flags[s >> 4]) g_cnt[(b2*Hh + h)*Ss + s] = 0;
    }
}

// ---------------- K4: candidate selection, worklist-driven -------------------------
__global__ void k_select_q() {
    __shared__ unsigned hks[Ss];
    __shared__ unsigned sks[Ss];
    __shared__ unsigned comb[TI][Ss/32];
    __shared__ unsigned uni[TI][Ss/32];
    __shared__ unsigned myh[TI], mys[TI];
    __shared__ int cnts[TI];
    __shared__ unsigned keys[Ss];
    __shared__ unsigned hist[256];
    __shared__ float qrow[GDd];
    __shared__ unsigned sDigit;
    __shared__ int sWant;

    int tid = threadIdx.x;
    int warp = tid >> 5, lane = tid & 31;
    int nwork = g_nwork;

    for (int w = blockIdx.x; w < nwork; w += 64) {
        int ht = g_work[w];
        int h = ht >> 6, tile = ht & 63;
        int it0 = tile * TI;
        for (int b = 0; b < Bb; ++b) {
            int bh = b*Hh + h;
            for (int t = tid; t < TI*(Ss/32); t += 256) ((unsigned*)uni)[t] = 0u;

            for (int g = 0; g < Gg; ++g) {
                for (int t = tid; t < Ss; t += 256) {
                    hks[t] = g_hk[(bh*Gg + g)*Ss + t];
                    sks[t] = g_sk[(h*Gg + g)*Ss + t];
                }
                if (tid < TI) {
                    myh[tid] = g_hq[(bh*Gg + g)*Ss + it0 + tid];
                    mys[tid] = g_sq[(h*Gg + g)*Ss + it0 + tid];
                }
                __syncthreads();

                #pragma unroll
                for (int iw = 0; iw < 2; ++iw) {
                    int ii = warp*2 + iw;
                    unsigned mh = myh[ii], ms = mys[ii];
                    int cnt = 0;
                    for (int c = 0; c < Ss/32; ++c) {
                        int j = c*32 + lane;
                        unsigned x = mh ^ hks[j];
                        bool m = (((x - 0x01010101u) & ~x & 0x80808080u) != 0u) && (sks[j] == ms);
                        unsigned bal = __ballot_sync(0xffffffffu, m);
                        if (lane == 0) comb[ii][c] = bal;
                        cnt += __popc(bal);
                    }
                    if (lane == 0) cnts[ii] = cnt;
                }
                __syncthreads();

                // rare path: count > KMAX needs group-sim dots + radix threshold
                for (int ii = 0; ii < TI; ++ii) {
                    if (cnts[ii] > KMAX) {
                        if (tid < GDd) qrow[tid] = g_qup[(bh*Ss + it0 + ii)*DKk + g*GDd + tid];
                        __syncthreads();
                        for (int j = tid; j < Ss; j += 256) {
                            unsigned key = 0u;
                            if ((comb[ii][j >> 5] >> (j & 31)) & 1u) {
                                const float* kr = g_kup + (bh*Ss + j)*DKk + g*GDd;
                                float sd = 0.f;
                                #pragma unroll
                                for (int d = 0; d < GDd; ++d) sd += qrow[d]*kr[d];
                                unsigned u = __float_as_uint(sd);
                                key = (u & 0x80000000u) ? ~u : (u | 0x80000000u);
                            }
                            keys[j] = key;
                        }
                        __syncthreads();
                        unsigned prefix = 0u, himask = 0u;
                        int want = KMAX;
                        for (int pass = 0; pass < 4; ++pass) {
                            int shift = 24 - 8*pass;
                            hist[tid] = 0u;
                            __syncthreads();
                            for (int j = tid; j < Ss; j += 256) {
                                unsigned k2 = keys[j];
                                if ((k2 & himask) == prefix) atomicAdd(&hist[(k2 >> shift) & 255], 1u);
                            }
                            __syncthreads();
                            for (int off = 1; off < 256; off <<= 1) {
                                unsigned add = (tid + off < 256) ? hist[tid + off] : 0u;
                                __syncthreads();
                                hist[tid] += add;
                                __syncthreads();
                            }
                            unsigned sfx = hist[tid];
                            unsigned nxt = (tid < 255) ? hist[tid + 1] : 0u;
                            if (sfx >= (unsigned)want && nxt < (unsigned)want) {
                                sDigit = (unsigned)tid;
                                sWant = want - (int)nxt;
                            }
                            __syncthreads();
                            prefix |= sDigit << shift;
                            himask |= 0xFFu << shift;
                            want = sWant;
                            __syncthreads();
                        }
                        unsigned thresh = prefix;
                        for (int j = tid; j < Ss; j += 256)
                            if (((comb[ii][j >> 5] >> (j & 31)) & 1u) && keys[j] >= thresh)
                                atomicOr(&uni[ii][j >> 5], 1u << (j & 31));
                        __syncthreads();
                    }
                }

                for (int t = tid; t < TI*(Ss/32); t += 256) {
                    int ii = t >> 5, w2 = t & 31;
                    if (cnts[ii] <= KMAX) uni[ii][w2] |= comb[ii][w2];
                }
                __syncthreads();
            }

            #pragma unroll
            for (int iw = 0; iw < 2; ++iw) {
                int ii = warp*2 + iw;
                unsigned w32 = uni[ii][lane];
                int pc = __popc(w32);
                int inc = pc;
                #pragma unroll
                for (int off = 1; off < 32; off <<= 1) {
                    int v = __shfl_up_sync(0xffffffffu, inc, off);
                    if (lane >= off) inc += v;
                }
                int pos = inc - pc;
                int outBase = (bh*Ss + it0 + ii)*KMAX;
                unsigned w2 = w32;
                while (w2 && pos < KMAX) {
                    int bit = __ffs(w2) - 1;
                    w2 &= w2 - 1u;
                    g_cand[outBase + pos] = lane*32 + bit;
                    ++pos;
                }
                int tot = __shfl_sync(0xffffffffu, inc, 31);
                if (lane == 0) g_cnt[bh*Ss + it0 + ii] = min(tot, KMAX);
            }
            __syncthreads();
        }
    }
}

// ---------------- K5: fused sparse attention + on-demand vproj + output GEMM -------
__global__ void k_attn_out(const float* __restrict__ Wo, const float* __restrict__ value,
                           const float* __restrict__ Wv, float* __restrict__ out) {
    __shared__ int cnt8[Hh];
    __shared__ float rowv[Hh*DKk];
    __shared__ float q64[DKk];
    __shared__ float red[DKk];
    __shared__ float pp[KMAX];
    __shared__ int cj[KMAX];
    __shared__ float pv[Dd];
    int tid = threadIdx.x;
    int row0 = blockIdx.x * 8;

    for (int rr = 0; rr < 8; ++rr) {
        int row = row0 + rr;
        int b = row >> 10, i = row & 1023;
        if (tid < Hh) cnt8[tid] = g_cnt[(b*Hh + tid)*Ss + i];
        __syncthreads();
        int any = 0;
        #pragma unroll
        for (int h2 = 0; h2 < Hh; ++h2) any |= cnt8[h2];
        float* orow = out + row*Dd;
        if (!any) {
            if (tid < 128) ((float4*)orow)[tid] = make_float4(0.f, 0.f, 0.f, 0.f);
            __syncthreads();
            continue;
        }
        for (int h2 = 0; h2 < Hh; ++h2) {
            int cn = cnt8[h2];
            if (cn == 0) {
                if (tid < DKk) rowv[h2*DKk + tid] = 0.f;
                __syncthreads();
                continue;
            }
            int bh = b*Hh + h2;
            if (tid < DKk) q64[tid] = g_qup[(bh*Ss + i)*DKk + tid];
            if (tid < cn) cj[tid] = g_cand[(bh*Ss + i)*KMAX + tid];
            __syncthreads();
            float s = -3.4e38f;
            if (tid < cn) {
                const float* kr = g_kup + (bh*Ss + cj[tid])*DKk;
                float acc = 0.f;
                #pragma unroll
                for (int d = 0; d < DKk; ++d) acc += q64[d]*kr[d];
                s = acc * 0.125f;
            }
            if (tid < DKk) red[tid] = s;
            __syncthreads();
            for (int off = 32; off >= 1; off >>= 1) {
                if (tid < off) red[tid] = fmaxf(red[tid], red[tid + off]);
                __syncthreads();
            }
            float mx = red[0];
            __syncthreads();
            float e = (tid < cn) ? expf(s - mx) : 0.f;
            if (tid < DKk) red[tid] = e;
            __syncthreads();
            for (int off = 32; off >= 1; off >>= 1) {
                if (tid < off) red[tid] += red[tid + off];
                __syncthreads();
            }
            float denom = red[0];
            if (tid < DKk) pp[tid] = e / denom;
            __syncthreads();
            // pv[d] = sum_c pp[c] * value[b, cj[c], d]
            for (int d = tid; d < Dd; d += 256) {
                float a = 0.f;
                for (int c = 0; c < cn; ++c) a += pp[c]*value[(b*Ss + cj[c])*Dd + d];
                pv[d] = a;
            }
            __syncthreads();
            // rowv[h2*DKk + dk] = sum_d pv[d] * Wv[h2, d, dk]
            if (tid < DKk) {
                float a = 0.f;
                for (int d = 0; d < Dd; ++d) a += pv[d]*Wv[(h2*Dd + d)*DKk + tid];
                rowv[h2*DKk + tid] = a;
            }
            __syncthreads();
        }
        float a0 = 0.f, a1 = 0.f;
        for (int k2 = 0; k2 < Hh*DKk; ++k2) {
            float rv = rowv[k2];
            if (rv == 0.f) continue;
            a0 += rv * Wo[k2*Dd + tid];
            a1 += rv * Wo[k2*Dd + tid + 256];
        }
        orow[tid] = a0;
        orow[tid + 256] = a1;
        __syncthreads();
    }
}

// ---------------- launch -----------------------------------------------------------
extern "C" void kernel_launch(void* const* d_in, const int* in_sizes, int n_in,
                              void* d_out, int out_size) {
    const float* query = (const float*)d_in[0];
    const float* key   = (const float*)d_in[1];
    const float* value = (const float*)d_in[2];
    const float* Aq    = (const float*)d_in[3];
    const float* Bq    = (const float*)d_in[4];
    const float* Ak    = (const float*)d_in[5];
    const float* Bk    = (const float*)d_in[6];
    const float* Wv    = (const float*)d_in[7];
    const float* Wo    = (const float*)d_in[8];
    const float* lsh   = (const float*)d_in[9];
    float* out = (float*)d_out;

    k_lowrank_gemm<<<dim3(16, KSPLIT, 2), 256>>>(query, key, Aq, Ak);
    k_upproj_hash<<<Bb*Hh*(Ss/16), 256>>>(Bq, Bk, lsh);
    k_trie<<<Hh, 256>>>();
    k_select_q<<<64, 256>>>();
    k_attn_out<<<Bb*Ss/8, 256>>>(Wo, value, Wv, out);
}